// round 13
// baseline (speedup 1.0000x reference)
#include <cuda_runtime.h>
#include <cstdint>

#define NB   2048
#define CELL 512
#define NK   30
#define LP   1024
#define NV   80
#define N3K  90

#define TB        320
#define NCTAS     296            // 2 per SM, one wave
#define S_STAGES  8
#define ROWS_PC   32
#define CB        (ROWS_PC * NV * 4)   // 10240 B
#define CPR       (LP / ROWS_PC)       // 32 chunks per row

// ---- dynamic smem layout ----
#define OFF_RING   0
#define OFF_SPHI   (S_STAGES * CB)                 // 81920: 2 x 1028 floats
#define OFF_SACC   (OFF_SPHI + 2 * 1028 * 4)       // 90144
#define OFF_SX     (OFF_SACC + 16 * NV * 4)        // 95264
#define OFF_SRAW   (OFF_SX + CELL * 4)             // 97312
#define OFF_SA     (OFF_SRAW + 384)
#define OFF_SB     (OFF_SA + 128)
#define OFF_SK     (OFF_SB + 128)
#define OFF_MBAR   (OFF_SK + 128)
#define SMEM_TOTAL (OFF_MBAR + 128 + 16)

__device__ __forceinline__ float ex2f(float v) {
    float r; asm("ex2.approx.ftz.f32 %0, %1;" : "=f"(r) : "f"(v)); return r;
}
__device__ __forceinline__ uint32_t s2u(const void* p) {
    uint32_t a;
    asm("{ .reg .u64 t; cvta.to.shared.u64 t, %1; cvt.u32.u64 %0, t; }" : "=r"(a) : "l"(p));
    return a;
}
__device__ __forceinline__ void mbar_init(uint32_t m, uint32_t cnt) {
    asm volatile("mbarrier.init.shared.b64 [%0], %1;" :: "r"(m), "r"(cnt) : "memory");
}
__device__ __forceinline__ void mbar_expect_tx(uint32_t m, uint32_t bytes) {
    asm volatile("mbarrier.arrive.expect_tx.shared.b64 _, [%0], %1;" :: "r"(m), "r"(bytes) : "memory");
}
__device__ __forceinline__ void mbar_arrive(uint32_t m) {
    asm volatile("mbarrier.arrive.shared.b64 _, [%0];" :: "r"(m) : "memory");
}
__device__ __forceinline__ void mbar_wait(uint32_t m, uint32_t parity) {
    asm volatile(
        "{\n\t.reg .pred P;\n\t"
        "WL_%=:\n\t"
        "mbarrier.try_wait.parity.acquire.cta.shared::cta.b64 P, [%0], %1, 0x989680;\n\t"
        "@!P bra WL_%=;\n\t"
        "}" :: "r"(m), "r"(parity) : "memory");
}
__device__ __forceinline__ void bulk_g2s(uint32_t dst, const void* src, uint32_t bytes, uint32_t mbar) {
    asm volatile(
        "cp.async.bulk.shared::cluster.global.mbarrier::complete_tx::bytes [%0], [%1], %2, [%3];"
        :: "r"(dst), "l"(src), "r"(bytes), "r"(mbar) : "memory");
}

// one 512-dot for output j against sx; lane0 stores pre-activation to sraw[j]
__device__ __forceinline__ void dot_one(
    int j, const float* sx, const float* __restrict__ W,
    const float* __restrict__ bias, float* sraw, int lane)
{
    const float4* wp = (const float4*)(W + (size_t)j * CELL) + lane;
    const float4* sp = (const float4*)sx + lane;
    float4 w0 = wp[0], w1 = wp[32], w2 = wp[64], w3 = wp[96];
    float4 x0 = sp[0], x1 = sp[32], x2 = sp[64], x3 = sp[96];
    float a = w0.x * x0.x;
    a = fmaf(w0.y, x0.y, a); a = fmaf(w0.z, x0.z, a); a = fmaf(w0.w, x0.w, a);
    a = fmaf(w1.x, x1.x, a); a = fmaf(w1.y, x1.y, a);
    a = fmaf(w1.z, x1.z, a); a = fmaf(w1.w, x1.w, a);
    a = fmaf(w2.x, x2.x, a); a = fmaf(w2.y, x2.y, a);
    a = fmaf(w2.z, x2.z, a); a = fmaf(w2.w, x2.w, a);
    a = fmaf(w3.x, x3.x, a); a = fmaf(w3.y, x3.y, a);
    a = fmaf(w3.z, x3.z, a); a = fmaf(w3.w, x3.w, a);
    #pragma unroll
    for (int o = 16; o; o >>= 1)
        a += __shfl_xor_sync(0xffffffffu, a, o);
    if (lane == 0) sraw[j] = a + bias[j];
}

__device__ __forceinline__ float phi_at(
    int l, const float* sa, const float* sb, const float* sk)
{
    const float fl = (float)l;
    float acc = 0.f;
    #pragma unroll
    for (int k = 0; k < NK; k++) {
        const float d = sk[k] - fl;
        acc = fmaf(sa[k], ex2f(-sb[k] * (d * d)), acc);
    }
    return acc;
}

// ---------------------------------------------------------------------------
__global__ void __launch_bounds__(TB, 2) kFused(
    const float* __restrict__ x,  const float* __restrict__ kold,
    const float* __restrict__ oh, const float* __restrict__ tlen,
    const float* __restrict__ W,  const float* __restrict__ bias,
    float* __restrict__ out)
{
    extern __shared__ __align__(128) char sm[];
    float* sphiB = (float*)(sm + OFF_SPHI);           // 2 x 1028
    float (*sacc)[NV] = (float(*)[NV])(sm + OFF_SACC);
    float* sx   = (float*)(sm + OFF_SX);
    float* sraw = (float*)(sm + OFF_SRAW);
    float* sa   = (float*)(sm + OFF_SA);
    float* sb   = (float*)(sm + OFF_SB);
    float* sk   = (float*)(sm + OFF_SK);

    const int t    = threadIdx.x;
    const int warp = t >> 5;
    const int lane = t & 31;
    const int r0   = t / 20;
    const int c20  = t % 20;

    // contiguous row block per CTA: first 272 CTAs get 7 rows, rest 6
    int start, nrows;
    if (blockIdx.x < 272) { start = blockIdx.x * 7; nrows = 7; }
    else { start = 1904 + (blockIdx.x - 272) * 6; nrows = 6; }
    const int totc = nrows * CPR;

    const uint32_t smem_base = s2u(sm);
    const uint32_t ring_u    = smem_base + OFF_RING;
    const uint32_t mb        = smem_base + OFF_MBAR;
    #define FULLB(s)  (mb + (s) * 16)
    #define EMPTYB(s) (mb + (s) * 16 + 8)

    const char* gsrc = (const char*)oh + (size_t)start * LP * NV * 4;
    const float4* ring4 = (const float4*)(sm + OFF_RING);

    float* okappa = out + (size_t)NB * NV;
    float* ophi   = out + (size_t)NB * NV + (size_t)NB * NK;

    if (t == 0) {
        #pragma unroll
        for (int s = 0; s < S_STAGES; s++) { mbar_init(FULLB(s), 1); mbar_init(EMPTYB(s), TB); }
    }
    __syncthreads();

    // ---- prime ring (DRAM flows during row-0 prologue) ----
    if (t == 0) {
        #pragma unroll
        for (int c = 0; c < S_STAGES; c++) {
            mbar_expect_tx(FULLB(c), CB);
            bulk_g2s(ring_u + c * CB, gsrc + (size_t)c * CB, CB, FULLB(c));
        }
    }

    // ---- row-0 full prologue ----
    {
        const float4* xr = (const float4*)(x + (size_t)start * CELL);
        if (t < 128) ((float4*)sx)[t] = xr[t];
        __syncthreads();
        #pragma unroll
        for (int i = 0; i < 9; i++) dot_one(warp * 9 + i, sx, W, bias, sraw, lane);
        __syncthreads();
        if (t < N3K) sraw[t] = __expf(sraw[t]);
        __syncthreads();
        if (t < NK) {
            const float inv = 1024.0f / tlen[start];
            sa[t] = sraw[t] * inv;
            sb[t] = sraw[NK + t] * 1.4426950408889634f;
            const float kap = kold[start * NK + t] + sraw[2 * NK + t];
            sk[t] = kap;
            okappa[(size_t)start * NK + t] = kap;
        }
        __syncthreads();
        float* ph = ophi + (size_t)start * (LP + 1);
        for (int l = t; l <= LP; l += TB) {
            const float p = phi_at(l, sa, sb, sk);
            sphiB[l] = p;       // buffer 0
            ph[l] = p;
        }
        __syncthreads();
    }

    float4 a0 = make_float4(0.f, 0.f, 0.f, 0.f);

    for (int idx = 0; idx < nrows; idx++) {
        const int   row  = start + idx;
        const int   nr   = row + 1;               // next row (global)
        const bool  hn   = (idx + 1 < nrows);
        float* sphiC = sphiB + (idx & 1) * 1028;
        float* sphiN = sphiB + ((idx + 1) & 1) * 1028;

        for (int cin = 0; cin < CPR; cin++) {
            const int gc = idx * CPR + cin;
            const int s  = gc & (S_STAGES - 1);
            const uint32_t par = (gc >> 3) & 1;

            mbar_wait(FULLB(s), par);
            const float4 v0 = ring4[s * (CB / 16) + t];
            const float4 v1 = ring4[s * (CB / 16) + t + TB];
            const float ph0 = sphiC[cin * ROWS_PC + r0];
            const float ph1 = sphiC[cin * ROWS_PC + 16 + r0];
            a0.x = fmaf(ph0, v0.x, a0.x); a0.y = fmaf(ph0, v0.y, a0.y);
            a0.z = fmaf(ph0, v0.z, a0.z); a0.w = fmaf(ph0, v0.w, a0.w);
            a0.x = fmaf(ph1, v1.x, a0.x); a0.y = fmaf(ph1, v1.y, a0.y);
            a0.z = fmaf(ph1, v1.z, a0.z); a0.w = fmaf(ph1, v1.w, a0.w);
            mbar_arrive(EMPTYB(s));

            if (t == 0 && gc + S_STAGES < totc) {
                mbar_wait(EMPTYB(s), par);
                mbar_expect_tx(FULLB(s), CB);
                bulk_g2s(ring_u + s * CB, gsrc + (size_t)(gc + S_STAGES) * CB, CB, FULLB(s));
            }

            // ---- next-row prologue, one piece per chunk (chunks 2..17) ----
            if (hn && cin >= 2 && cin < 18) {
                const int p = cin - 2;
                __syncthreads();
                if (p == 0) {
                    const float4* xr = (const float4*)(x + (size_t)nr * CELL);
                    if (t < 128) ((float4*)sx)[t] = xr[t];
                } else if (p <= 9) {
                    dot_one(warp * 9 + (p - 1), sx, W, bias, sraw, lane);
                } else if (p == 10) {
                    if (t < N3K) sraw[t] = __expf(sraw[t]);
                } else if (p == 11) {
                    if (t < NK) {
                        const float inv = 1024.0f / tlen[nr];
                        sa[t] = sraw[t] * inv;
                        sb[t] = sraw[NK + t] * 1.4426950408889634f;
                        const float kap = kold[nr * NK + t] + sraw[2 * NK + t];
                        sk[t] = kap;
                        okappa[(size_t)nr * NK + t] = kap;
                    }
                } else {
                    const int q = p - 12;
                    float* phg = ophi + (size_t)nr * (LP + 1);
                    if (t < 256) {
                        const int l = q * 256 + t;
                        const float pv = phi_at(l, sa, sb, sk);
                        sphiN[l] = pv; phg[l] = pv;
                    } else if (q == 0 && t == 256) {
                        const float pv = phi_at(LP, sa, sb, sk);
                        sphiN[LP] = pv; phg[LP] = pv;
                    }
                }
            }
        }

        // ---- row epilogue: reduce sacc -> w ----
        ((float4*)&sacc[r0][0])[c20] = a0;
        __syncthreads();
        for (int v = t; v < NV; v += TB) {
            float ssum = 0.f;
            #pragma unroll
            for (int i = 0; i < 16; i++) ssum += sacc[i][v];
            out[(size_t)row * NV + v] = ssum;
        }
        a0 = make_float4(0.f, 0.f, 0.f, 0.f);
        __syncthreads();
    }
}

// ---------------------------------------------------------------------------
extern "C" void kernel_launch(void* const* d_in, const int* in_sizes, int n_in,
                              void* d_out, int out_size)
{
    const float* x    = (const float*)d_in[0];
    const float* kold = (n_in > 1) ? (const float*)d_in[1] : nullptr;
    const float* oh   = (n_in > 2) ? (const float*)d_in[2] : nullptr;
    const float* tl   = (n_in > 3) ? (const float*)d_in[3] : nullptr;
    const float* W    = (n_in > 4) ? (const float*)d_in[4] : nullptr;
    const float* bias = (n_in > 5) ? (const float*)d_in[5] : nullptr;

    for (int i = 0; i < n_in; i++) {
        switch (in_sizes[i]) {
            case NB * CELL:            x    = (const float*)d_in[i]; break;
            case NB * NK:              kold = (const float*)d_in[i]; break;
            case NB * LP * NV:         oh   = (const float*)d_in[i]; break;
            case NB:                   tl   = (const float*)d_in[i]; break;
            case N3K * CELL:           W    = (const float*)d_in[i]; break;
            case N3K:                  bias = (const float*)d_in[i]; break;
            default: break;
        }
    }

    cudaFuncSetAttribute(kFused, cudaFuncAttributeMaxDynamicSharedMemorySize, SMEM_TOTAL);
    float* out = (float*)d_out;
    kFused<<<NCTAS, TB, SMEM_TOTAL>>>(x, kold, oh, tl, W, bias, out);
}